// round 6
// baseline (speedup 1.0000x reference)
#include <cuda_runtime.h>

#define HH 256
#define WW 256
#define BB 8
#define IMG_PIX (HH*WW)          // 65536
#define NPIX (BB*IMG_PIX)        // 524288

#define RR 36                    // region side: 32 + 2*T, T=2
#define RC (RR*RR)               // 1296
#define NL 15                    // launches (15*2 = 30 iterations)

static __device__ float  g_gray[2][NPIX];
static __device__ float  g_s[2][NPIX];
static __device__ float4 g_cst[NPIX];     // {dx, dy, rho_c+EPS, th}
static __device__ float2 g_u[2][NPIX];
static __device__ float4 g_p[2][NPIX];
static __device__ int    g_mn, g_mx;

__constant__ float GW[25] = {
    0.000874f, 0.006976f, 0.01386f,  0.006976f, 0.000874f,
    0.006976f, 0.0557f,   0.110656f, 0.0557f,   0.006976f,
    0.01386f,  0.110656f, 0.219833f, 0.110656f, 0.01386f,
    0.006976f, 0.0557f,   0.110656f, 0.0557f,   0.006976f,
    0.000874f, 0.006976f, 0.01386f,  0.006976f, 0.000874f
};

#define L_T    0.045f
#define THETA  0.3f
#define TAUT   0.8333333333333334f
#define EPSV   1e-12f

__device__ __forceinline__ float rsqrt_approx(float x){
    float y; asm("rsqrt.approx.f32 %0, %1;" : "=f"(y) : "f"(x)); return y;
}
__device__ __forceinline__ float rcp_approx(float x){
    float y; asm("rcp.approx.f32 %0, %1;" : "=f"(y) : "f"(x)); return y;
}

__global__ void k_init(){ g_mn = 0x7f7fffff; g_mx = 0; }

// gray conversion + global min/max reduction over BOTH images
__global__ __launch_bounds__(256) void k_gray(const float* __restrict__ x1,
                                              const float* __restrict__ x2)
{
    int idx = blockIdx.x*256 + threadIdx.x;     // < NPIX
    int b   = idx >> 16;
    int pix = idx & 65535;
    int o   = b*3*IMG_PIX + pix;
    float g1 = 0.114f*x1[o] + 0.587f*x1[o+IMG_PIX] + 0.299f*x1[o+2*IMG_PIX];
    float g2 = 0.114f*x2[o] + 0.587f*x2[o+IMG_PIX] + 0.299f*x2[o+2*IMG_PIX];
    g_gray[0][idx] = g1;
    g_gray[1][idx] = g2;
    float mn = fminf(g1, g2), mx = fmaxf(g1, g2);
    #pragma unroll
    for (int off = 16; off; off >>= 1){
        mn = fminf(mn, __shfl_xor_sync(0xffffffffu, mn, off));
        mx = fmaxf(mx, __shfl_xor_sync(0xffffffffu, mx, off));
    }
    __shared__ float smn[8], smx[8];
    int lane = threadIdx.x & 31, w = threadIdx.x >> 5;
    if (!lane){ smn[w] = mn; smx[w] = mx; }
    __syncthreads();
    if (threadIdx.x == 0){
        #pragma unroll
        for (int i = 1; i < 8; i++){ mn = fminf(mn, smn[i]); mx = fmaxf(mx, smx[i]); }
        atomicMin(&g_mn, __float_as_int(mn));   // values >= 0: int order == float order
        atomicMax(&g_mx, __float_as_int(mx));
    }
}

// normalize + 5x5 gaussian (zero SAME padding)
__global__ __launch_bounds__(256) void k_smooth()
{
    int img = blockIdx.z >> 3;
    int b   = blockIdx.z & 7;
    const float* gsrc = g_gray[img] + b*IMG_PIX;
    float mn = __int_as_float(g_mn);
    float mx = __int_as_float(g_mx);
    float scale = 255.0f / (mx - mn);
    __shared__ float sn[36*36];
    int tx0 = blockIdx.x*32, ty0 = blockIdx.y*32;
    int tid = threadIdx.x;
    for (int idx = tid; idx < 36*36; idx += 256){
        int li = idx/36, lj = idx - li*36;
        int gi = ty0 + li - 2, gj = tx0 + lj - 2;
        float v = 0.f;
        if ((unsigned)gi < HH && (unsigned)gj < WW) v = (gsrc[gi*WW+gj] - mn)*scale;
        sn[idx] = v;
    }
    __syncthreads();
    int lj = tid & 31, li0 = tid >> 5;
    #pragma unroll
    for (int r = 0; r < 4; r++){
        int li = li0 + r*8;
        float acc = 0.f;
        #pragma unroll
        for (int a = 0; a < 5; a++)
            #pragma unroll
            for (int c = 0; c < 5; c++)
                acc += GW[a*5+c]*sn[(li+a)*36 + lj + c];
        g_s[img][b*IMG_PIX + (ty0+li)*WW + tx0+lj] = acc;
    }
}

// centered grad of s2, per-pixel constants, zero-init state
__global__ __launch_bounds__(256) void k_prep()
{
    int idx = blockIdx.x*256 + threadIdx.x;
    int b = idx >> 16, pix = idx & 65535;
    int i = pix >> 8, j = pix & 255;
    const float* s2 = g_s[1] + b*IMG_PIX;
    float c  = s2[pix];
    float xr = s2[i*WW + min(j+1, WW-1)];
    float xl = s2[i*WW + max(j-1, 0)];
    float yd = s2[min(i+1, HH-1)*WW + j];
    float yu = s2[max(i-1, 0)*WW + j];
    float dx = 0.5f*(xr - xl);
    float dy = 0.5f*(yd - yu);
    float grad = dx*dx + dy*dy + EPSV;
    float rho_c = c - g_s[0][idx] + EPSV;
    g_cst[idx] = make_float4(dx, dy, rho_c, L_T*grad);
    g_u[0][idx] = make_float2(0.f, 0.f);
    g_p[0][idx] = make_float4(0.f, 0.f, 0.f, 0.f);
}

// Two fused TV-L1 iterations on a 32x32 tile; 36x36 region in smem.
// Windows: u1 [1,36)  p1 [1,35)  u2 [2,35)  p2 [2,34)=interior.
// Out-of-image region cells stay 0 (masked), preserving the invariant that
// p11/p21 == 0 on the last image column and p12/p22 == 0 on the last image
// row, so the u-pass divergence needs no boundary predicates.
__global__ void __launch_bounds__(256, 4) k_fused2(int s, int lastL,
                                                   float* __restrict__ out)
{
    extern __shared__ char sraw[];
    float4* sp   = (float4*)sraw;            // RC float4 (p)
    float4* scst = sp + RC;                  // RC float4 (cst)
    float2* su   = (float2*)(scst + RC);     // RC float2 (u)

    const int tid = threadIdx.x;
    const int tx0 = blockIdx.x*32, ty0 = blockIdx.y*32, b = blockIdx.z;
    const int base = b*IMG_PIX;
    const float4* __restrict__ p_in = g_p[s];
    const float2* __restrict__ u_in = g_u[s];
    float4* __restrict__ p_out = g_p[s^1];
    float2* __restrict__ u_out = g_u[s^1];

    // per-thread cell table (computed once)
    int  li_[6], lj_[6], g_[6];
    bool in_[6], bx_[6], by_[6], act_[6];
    #pragma unroll
    for (int k = 0; k < 6; k++){
        int idx = tid + 256*k;
        bool act = (k < 5) | (tid < (RC - 1280));   // idx < 1296
        int li = idx / RR;
        int lj = idx - li*RR;
        int gi = ty0 + li - 2, gj = tx0 + lj - 2;
        bool in = act && ((unsigned)gi < HH) && ((unsigned)gj < WW);
        li_[k] = li; lj_[k] = lj;
        g_[k]  = base + gi*WW + gj;
        in_[k] = in; act_[k] = act;
        bx_[k] = (gj == WW-1); by_[k] = (gi == HH-1);
    }

    // ---- stage ----
    #pragma unroll
    for (int k = 0; k < 6; k++){
        if (!act_[k]) break;
        int idx = tid + 256*k;
        if (in_[k]){
            int g = g_[k];
            sp[idx]   = __ldg(&p_in[g]);
            su[idx]   = __ldg(&u_in[g]);
            scst[idx] = __ldg(&g_cst[g]);
        } else {
            sp[idx]   = make_float4(0.f,0.f,0.f,0.f);
            su[idx]   = make_float2(0.f,0.f);
            scst[idx] = make_float4(0.f,0.f,0.f, L_T*EPSV);
        }
    }
    __syncthreads();

    #pragma unroll
    for (int t = 0; t < 2; t++){
        const int lo  = 1 + t;
        const int hiU = 36 - t;     // u window upper (exclusive)
        const int hiP = 35 - t;     // p window upper (exclusive)
        const bool finalU = lastL && (t == 1);
        const bool finalP = (t == 1);

        // ---- u pass ----
        #pragma unroll
        for (int k = 0; k < 6; k++){
            int li = li_[k], lj = lj_[k];
            if (!in_[k] || li < lo || li >= hiU || lj < lo || lj >= hiU) continue;
            int idx = tid + 256*k;
            float4 c = scst[idx];
            float2 u = su[idx];
            float rho = c.z + c.x*u.x + c.y*u.y;
            float ig  = L_T * rcp_approx(c.w);
            float coef = (rho < -c.w) ? L_T : ((rho > c.w) ? -L_T : -rho*ig);
            float4 pc = sp[idx];
            float4 pl = sp[idx-1];
            float4 pu = sp[idx-RR];
            float2 un;
            un.x = fmaf(coef, c.x, u.x) + THETA*(pc.x - pl.x + pc.y - pu.y);
            un.y = fmaf(coef, c.y, u.y) + THETA*(pc.z - pl.z + pc.w - pu.w);
            su[idx] = un;
            if (finalU && li < 34 && lj < 34)
                out[b*3*IMG_PIX + 2*IMG_PIX + (g_[k] - base)] = rho;
        }
        __syncthreads();

        // ---- p pass ----
        #pragma unroll
        for (int k = 0; k < 6; k++){
            int li = li_[k], lj = lj_[k];
            if (!in_[k] || li < lo || li >= hiP || lj < lo || lj >= hiP) continue;
            int idx = tid + 256*k;
            float2 uc = su[idx];
            float2 ur = su[idx+1];
            float2 ud = su[idx+RR];
            float u1x = bx_[k] ? 0.f : ur.x - uc.x;
            float u2x = bx_[k] ? 0.f : ur.y - uc.y;
            float u1y = by_[k] ? 0.f : ud.x - uc.x;
            float u2y = by_[k] ? 0.f : ud.y - uc.y;
            float s1 = u1x*u1x + u1y*u1y + EPSV;
            float s2 = u2x*u2x + u2y*u2y + EPSV;
            float ng1 = 1.f + TAUT*(s1*rsqrt_approx(s1));
            float ng2 = 1.f + TAUT*(s2*rsqrt_approx(s2));
            float r1 = rcp_approx(ng1), r2 = rcp_approx(ng2);
            float4 p = sp[idx];
            float4 pn = make_float4((p.x + TAUT*u1x)*r1, (p.y + TAUT*u1y)*r1,
                                    (p.z + TAUT*u2x)*r2, (p.w + TAUT*u2y)*r2);
            if (!finalP){
                sp[idx] = pn;
            } else {
                // p2 window == interior: write results straight to global
                int g = g_[k];
                if (lastL){
                    int ob = b*3*IMG_PIX + (g - base);
                    out[ob]           = uc.x;
                    out[ob + IMG_PIX] = uc.y;
                } else {
                    p_out[g] = pn;
                    u_out[g] = uc;
                }
            }
        }
        if (!finalP) __syncthreads();
    }
}

#define SMEM_BYTES (RC*(16+16+8))   // 51840

extern "C" void kernel_launch(void* const* d_in, const int* in_sizes, int n_in,
                              void* d_out, int out_size)
{
    const float* x1 = (const float*)d_in[0];
    const float* x2 = (const float*)d_in[1];
    float* out = (float*)d_out;

    cudaFuncSetAttribute(k_fused2, cudaFuncAttributeMaxDynamicSharedMemorySize,
                         SMEM_BYTES);

    k_init<<<1, 1>>>();
    k_gray<<<NPIX/256, 256>>>(x1, x2);
    dim3 gB(8, 8, 16);
    k_smooth<<<gB, 256>>>();
    k_prep<<<NPIX/256, 256>>>();
    dim3 gI(8, 8, 8);
    for (int L = 0; L < NL; ++L)
        k_fused2<<<gI, 256, SMEM_BYTES>>>(L & 1, L == NL-1, out);
}

// round 7
// speedup vs baseline: 1.1130x; 1.1130x over previous
#include <cuda_runtime.h>

#define HH 256
#define WW 256
#define BB 8
#define IMG_PIX (HH*WW)          // 65536
#define NPIX (BB*IMG_PIX)        // 524288

static __device__ float  g_gray[2][NPIX];
static __device__ float4 g_cst[NPIX];     // {dx, dy, rho_c+EPS, th}
static __device__ float2 g_u[2][NPIX];
static __device__ float4 g_p[2][NPIX];
static __device__ int    g_mn, g_mx;

__constant__ float GW[25] = {
    0.000874f, 0.006976f, 0.01386f,  0.006976f, 0.000874f,
    0.006976f, 0.0557f,   0.110656f, 0.0557f,   0.006976f,
    0.01386f,  0.110656f, 0.219833f, 0.110656f, 0.01386f,
    0.006976f, 0.0557f,   0.110656f, 0.0557f,   0.006976f,
    0.000874f, 0.006976f, 0.01386f,  0.006976f, 0.000874f
};

#define L_T    0.045f
#define THETA  0.3f
#define TAUT   0.8333333333333334f
#define EPSV   1e-12f

__device__ __forceinline__ float rsqrt_approx(float x){
    float y; asm("rsqrt.approx.f32 %0, %1;" : "=f"(y) : "f"(x)); return y;
}
__device__ __forceinline__ float rcp_approx(float x){
    float y; asm("rcp.approx.f32 %0, %1;" : "=f"(y) : "f"(x)); return y;
}

__global__ void k_init(){ g_mn = 0x7f7fffff; g_mx = 0; }

// gray conversion + global min/max reduction over BOTH images
__global__ __launch_bounds__(256) void k_gray(const float* __restrict__ x1,
                                              const float* __restrict__ x2)
{
    int idx = blockIdx.x*256 + threadIdx.x;     // < NPIX
    int b   = idx >> 16;
    int pix = idx & 65535;
    int o   = b*3*IMG_PIX + pix;
    float g1 = 0.114f*x1[o] + 0.587f*x1[o+IMG_PIX] + 0.299f*x1[o+2*IMG_PIX];
    float g2 = 0.114f*x2[o] + 0.587f*x2[o+IMG_PIX] + 0.299f*x2[o+2*IMG_PIX];
    g_gray[0][idx] = g1;
    g_gray[1][idx] = g2;
    float mn = fminf(g1, g2), mx = fmaxf(g1, g2);
    #pragma unroll
    for (int off = 16; off; off >>= 1){
        mn = fminf(mn, __shfl_xor_sync(0xffffffffu, mn, off));
        mx = fmaxf(mx, __shfl_xor_sync(0xffffffffu, mx, off));
    }
    __shared__ float smn[8], smx[8];
    int lane = threadIdx.x & 31, w = threadIdx.x >> 5;
    if (!lane){ smn[w] = mn; smx[w] = mx; }
    __syncthreads();
    if (threadIdx.x == 0){
        #pragma unroll
        for (int i = 1; i < 8; i++){ mn = fminf(mn, smn[i]); mx = fmaxf(mx, smx[i]); }
        atomicMin(&g_mn, __float_as_int(mn));   // values >= 0: int order == float order
        atomicMax(&g_mx, __float_as_int(mx));
    }
}

// Fused: normalize + 5x5 gaussian (both images) + centered grad of smooth(s2)
// + per-pixel constants + zero-init of u/p.  Eliminates the g_s round-trip.
__global__ __launch_bounds__(256) void k_fprep()
{
    __shared__ float sg1[38*38];   // normalized gray 1, tile + 3-halo
    __shared__ float sg2[38*38];   // normalized gray 2
    __shared__ float ss2[34*34];   // smoothed s2, tile + 1-halo

    const int b = blockIdx.z;
    const int tx0 = blockIdx.x*32, ty0 = blockIdx.y*32;
    const float mn = __int_as_float(g_mn);
    const float mx = __int_as_float(g_mx);
    const float scale = 255.0f / (mx - mn);
    const float* __restrict__ G1 = g_gray[0] + b*IMG_PIX;
    const float* __restrict__ G2 = g_gray[1] + b*IMG_PIX;
    const int tid = threadIdx.x;

    for (int idx = tid; idx < 38*38; idx += 256){
        int li = idx/38, lj = idx - li*38;
        int gi = ty0 + li - 3, gj = tx0 + lj - 3;
        float v1 = 0.f, v2 = 0.f;
        if (((unsigned)gi < HH) && ((unsigned)gj < WW)){
            int g = gi*WW + gj;
            v1 = (G1[g] - mn)*scale;
            v2 = (G2[g] - mn)*scale;
        }
        sg1[idx] = v1; sg2[idx] = v2;
    }
    __syncthreads();

    for (int idx = tid; idx < 34*34; idx += 256){
        int li = idx/34, lj = idx - li*34;
        float acc = 0.f;
        #pragma unroll
        for (int a = 0; a < 5; a++)
            #pragma unroll
            for (int c = 0; c < 5; c++)
                acc += GW[a*5+c]*sg2[(li+a)*38 + lj + c];
        ss2[idx] = acc;
    }
    __syncthreads();

    const int lj = tid & 31, li0 = tid >> 5;
    #pragma unroll
    for (int r = 0; r < 4; r++){
        int li = li0 + r*8;                 // 0..31
        int gi = ty0 + li, gj = tx0 + lj;
        float s1 = 0.f;
        #pragma unroll
        for (int a = 0; a < 5; a++)
            #pragma unroll
            for (int c = 0; c < 5; c++)
                s1 += GW[a*5+c]*sg1[(li+1+a)*38 + lj+1 + c];
        float cen = ss2[(li+1)*34 + lj+1];
        // centered grad with one-sided (clamped) borders, scaled 0.5
        int jr = min(gj+1, WW-1) - tx0 + 1;
        int jl = max(gj-1, 0)    - tx0 + 1;
        int id = min(gi+1, HH-1) - ty0 + 1;
        int iu = max(gi-1, 0)    - ty0 + 1;
        float dx = 0.5f*(ss2[(li+1)*34 + jr] - ss2[(li+1)*34 + jl]);
        float dy = 0.5f*(ss2[id*34 + lj+1]  - ss2[iu*34 + lj+1]);
        float grad = dx*dx + dy*dy + EPSV;
        int g = b*IMG_PIX + gi*WW + gj;
        g_cst[g]    = make_float4(dx, dy, cen - s1 + EPSV, L_T*grad);
        g_u[0][g]   = make_float2(0.f, 0.f);
        g_p[0][g]   = make_float4(0.f, 0.f, 0.f, 0.f);
    }
}

// u-update body. Valid only for in-image (gi,gj).
// Invariant: p11/p21 == 0 on the last image column and p12/p22 == 0 on the
// last image row (maintained by the p-pass boundary selects), so the
// divergence needs no right/bottom predicates; only up/left loads are guarded.
__device__ __forceinline__ float2 u_update(const float4* __restrict__ p_in,
                                           const float2* __restrict__ u_in,
                                           int g, int gi, int gj,
                                           float4& pc_out, float& rho_out)
{
    float4 c  = __ldg(&g_cst[g]);
    float2 u  = __ldg(&u_in[g]);
    float4 pc = __ldg(&p_in[g]);
    float4 pl = (gj > 0) ? __ldg(&p_in[g-1])  : make_float4(0.f,0.f,0.f,0.f);
    float4 pu = (gi > 0) ? __ldg(&p_in[g-WW]) : make_float4(0.f,0.f,0.f,0.f);
    pc_out = pc;
    float rho = c.z + c.x*u.x + c.y*u.y;
    rho_out = rho;
    float ig = L_T * rcp_approx(c.w);      // == 1/grad in effect (see invariant note)
    float coef = (rho < -c.w) ? L_T : ((rho > c.w) ? -L_T : -rho*ig);
    float d1 = pc.x - pl.x + pc.y - pu.y;
    float d2 = pc.z - pl.z + pc.w - pu.w;
    float2 un;
    un.x = fmaf(coef, c.x, u.x) + THETA*d1;
    un.y = fmaf(coef, c.y, u.y) + THETA*d2;
    return un;
}

// One TV-L1 iteration. 16x32 tile, 128 threads, 4 pixels/thread.
// 1024 blocks -> ~6.9/SM for good wave balance. u_new exchanged through smem
// (17x33 incl. right/down halo); everything else read from global (L1/L2).
__global__ __launch_bounds__(128) void k_iter(int s, int last, float* __restrict__ out)
{
    __shared__ float2 su[17*33];

    const int tx = threadIdx.x & 31, ty = threadIdx.x >> 5;   // ty in [0,4)
    const int tx0 = blockIdx.x*32, ty0 = blockIdx.y*16, b = blockIdx.z;
    const int base = b*IMG_PIX;
    const float4* __restrict__ p_in = g_p[s];
    const float2* __restrict__ u_in = g_u[s];
    float4* __restrict__ p_out = g_p[s^1];
    float2* __restrict__ u_out = g_u[s^1];

    float4 pc_r[4];

    // ---- u-pass: own 4 pixels (rows r*4 + ty) ----
    #pragma unroll
    for (int r = 0; r < 4; r++){
        int li = r*4 + ty;
        int gi = ty0 + li, gj = tx0 + tx;
        int g = base + gi*WW + gj;
        float rho;
        float2 un = u_update(p_in, u_in, g, gi, gj, pc_r[r], rho);
        su[li*33 + tx] = un;
        if (last) out[b*3*IMG_PIX + 2*IMG_PIX + gi*WW + gj] = rho;
    }
    // ---- u-pass halo: bottom row (warp 0), right column (warp 1) ----
    if (ty == 0){
        int gi = ty0 + 16, gj = tx0 + tx;
        if (gi < HH){
            int g = base + gi*WW + gj;
            float4 dummy; float rho;
            su[16*33 + tx] = u_update(p_in, u_in, g, gi, gj, dummy, rho);
        }
    } else if (ty == 1 && tx < 16){
        int gi = ty0 + tx, gj = tx0 + 32;
        if (gj < WW){
            int g = base + gi*WW + gj;
            float4 dummy; float rho;
            su[tx*33 + 32] = u_update(p_in, u_in, g, gi, gj, dummy, rho);
        }
    }
    __syncthreads();

    // ---- p-pass: own 4 pixels ----
    #pragma unroll
    for (int r = 0; r < 4; r++){
        int li = r*4 + ty;
        int gi = ty0 + li, gj = tx0 + tx;
        int g = base + gi*WW + gj;
        float2 uc = su[li*33 + tx];
        float2 ur = su[li*33 + tx + 1];
        float2 ud = su[(li+1)*33 + tx];
        bool bx = (gj == WW-1), by = (gi == HH-1);
        float u1x = bx ? 0.f : ur.x - uc.x;
        float u2x = bx ? 0.f : ur.y - uc.y;
        float u1y = by ? 0.f : ud.x - uc.x;
        float u2y = by ? 0.f : ud.y - uc.y;
        float s1 = u1x*u1x + u1y*u1y + EPSV;
        float s2 = u2x*u2x + u2y*u2y + EPSV;
        float ng1 = 1.f + TAUT*(s1*rsqrt_approx(s1));
        float ng2 = 1.f + TAUT*(s2*rsqrt_approx(s2));
        float r1 = rcp_approx(ng1), r2 = rcp_approx(ng2);
        float4 p = pc_r[r];
        if (last){
            int ob = b*3*IMG_PIX + gi*WW + gj;
            out[ob]           = uc.x;
            out[ob + IMG_PIX] = uc.y;
        } else {
            p_out[g] = make_float4((p.x + TAUT*u1x)*r1, (p.y + TAUT*u1y)*r1,
                                   (p.z + TAUT*u2x)*r2, (p.w + TAUT*u2y)*r2);
            u_out[g] = uc;
        }
    }
}

extern "C" void kernel_launch(void* const* d_in, const int* in_sizes, int n_in,
                              void* d_out, int out_size)
{
    const float* x1 = (const float*)d_in[0];
    const float* x2 = (const float*)d_in[1];
    float* out = (float*)d_out;

    k_init<<<1, 1>>>();
    k_gray<<<NPIX/256, 256>>>(x1, x2);
    dim3 gP(8, 8, 8);
    k_fprep<<<gP, 256>>>();
    dim3 gI(8, 16, 8);
    for (int it = 0; it < 30; ++it)
        k_iter<<<gI, 128>>>(it & 1, it == 29, out);
}